// round 4
// baseline (speedup 1.0000x reference)
#include <cuda_runtime.h>

#define NB 2
#define NS 2048
#define NHID 2048
#define NHEADS 16
#define HD 128
#define N3 6144

// Scratch (static __device__ arrays per allocation rules): ~134 MB total
__device__ float g_Q[NB*NHEADS*NS*HD];
__device__ float g_K[NB*NHEADS*NS*HD];
__device__ float g_V[NB*NHEADS*NS*HD];
__device__ float g_O[NB*NS*NHID];

// ---------------------------------------------------------------------------
// Tiled SGEMM: C[M,N] = A[M,K] @ B[K,N] + bias[N]
// MODE 0: A = x, epilogue scatters into g_Q/g_K/g_V ([b][head][s][d] layout)
// MODE 1: A = g_O (internal), epilogue writes C = final output
// BM=BN=128, BK=16, 256 threads, 8x8 register micro-tile per thread.
// ---------------------------------------------------------------------------
template<int MODE>
__global__ __launch_bounds__(256)
void sgemm_kernel(const float* __restrict__ A, const float* __restrict__ Bmat,
                  const float* __restrict__ bias, float* __restrict__ C,
                  int N, int K)
{
    constexpr int BM = 128, BN = 128, BK = 16;
    __shared__ float As[BK][BM];   // A stored transposed: As[k][m]
    __shared__ float Bs[BK][BN];

    const int tid = threadIdx.x;
    const int tx = tid & 15, ty = tid >> 4;
    const int mBase = blockIdx.y * BM;
    const int nBase = blockIdx.x * BN;

    const float* Ap = (MODE == 1) ? (const float*)g_O : A;

    float acc[8][8];
#pragma unroll
    for (int i = 0; i < 8; i++)
#pragma unroll
        for (int j = 0; j < 8; j++) acc[i][j] = 0.f;

    for (int kb = 0; kb < K; kb += BK) {
        // Load A tile (128 rows x 16 cols), store transposed
#pragma unroll
        for (int t = 0; t < 2; t++) {
            int idx = tid + t * 256;          // 512 float4 total
            int row = idx >> 2;               // 4 float4 per row
            int kc  = (idx & 3) << 2;
            float4 v = *(const float4*)(Ap + (size_t)(mBase + row) * K + kb + kc);
            As[kc + 0][row] = v.x;
            As[kc + 1][row] = v.y;
            As[kc + 2][row] = v.z;
            As[kc + 3][row] = v.w;
        }
        // Load B tile (16 rows x 128 cols)
#pragma unroll
        for (int t = 0; t < 2; t++) {
            int idx = tid + t * 256;
            int row = idx >> 5;               // 32 float4 per row
            int c4  = (idx & 31) << 2;
            *(float4*)&Bs[row][c4] =
                *(const float4*)(Bmat + (size_t)(kb + row) * N + nBase + c4);
        }
        __syncthreads();

#pragma unroll
        for (int kk = 0; kk < BK; kk++) {
            float a[8], b[8];
            *(float4*)&a[0] = *(float4*)&As[kk][ty * 8];
            *(float4*)&a[4] = *(float4*)&As[kk][ty * 8 + 4];
            *(float4*)&b[0] = *(float4*)&Bs[kk][tx * 8];
            *(float4*)&b[4] = *(float4*)&Bs[kk][tx * 8 + 4];
#pragma unroll
            for (int i = 0; i < 8; i++)
#pragma unroll
                for (int j = 0; j < 8; j++)
                    acc[i][j] = fmaf(a[i], b[j], acc[i][j]);
        }
        __syncthreads();
    }

    // Epilogue
    const int m0 = mBase + ty * 8;
    const int n0 = nBase + tx * 8;
    float4 bv0 = *(const float4*)(bias + n0);
    float4 bv1 = *(const float4*)(bias + n0 + 4);
#pragma unroll
    for (int i = 0; i < 8; i++) {
        int m = m0 + i;
#pragma unroll
        for (int jq = 0; jq < 2; jq++) {
            int n = n0 + jq * 4;
            float4 bv = jq ? bv1 : bv0;
            float4 r;
            r.x = acc[i][jq * 4 + 0] + bv.x;
            r.y = acc[i][jq * 4 + 1] + bv.y;
            r.z = acc[i][jq * 4 + 2] + bv.z;
            r.w = acc[i][jq * 4 + 3] + bv.w;
            if (MODE == 0) {
                // n -> (qkv_sel, head, d); m -> (b, s)
                int c    = n >> 11;          // n / 2048
                int rem  = n & 2047;
                int head = rem >> 7;
                int d    = rem & 127;
                int b    = m >> 11;          // m / S (S = 2048)
                int s    = m & 2047;
                float* dst = (c == 0) ? g_Q : ((c == 1) ? g_K : g_V);
                *(float4*)&dst[(size_t)((b * NHEADS + head) * NS + s) * HD + d] = r;
            } else {
                *(float4*)&C[(size_t)m * N + n] = r;
            }
        }
    }
}

// ---------------------------------------------------------------------------
// Causal flash attention, fp32 SIMT.
// Grid: (S/64 query tiles, B*NHEADS). 256 threads.
// 64x64 score tiles, D=128. Online softmax, skip key tiles > query tile.
// Matches reference numerics: masked scores -> exp underflows to exact 0,
// same as ref's flat -10000 mask value (real scores are O(1), so both give
// probability exactly 0 in fp32).
// ---------------------------------------------------------------------------
#define QS_STRIDE 132
#define KT_STRIDE 68
#define SS_STRIDE 68
#define ATTN_SMEM ((64*QS_STRIDE + 128*KT_STRIDE + 64*QS_STRIDE + 64*SS_STRIDE + 128) * sizeof(float))

__global__ __launch_bounds__(256)
void attn_kernel()
{
    extern __shared__ float sm[];
    float* Qs      = sm;                        // [64][132]
    float* Kt      = Qs + 64 * QS_STRIDE;       // [128][68]  (K transposed: Kt[d][kj])
    float* Vs      = Kt + 128 * KT_STRIDE;      // [64][132]
    float* Ssc     = Vs + 64 * QS_STRIDE;       // [64][68]
    float* alpha_sh = Ssc + 64 * SS_STRIDE;     // [64]
    float* l_sh     = alpha_sh + 64;            // [64]

    const int tid = threadIdx.x;
    const int bh  = blockIdx.y;                 // b*NHEADS + head
    const int qt  = blockIdx.x;
    const int q0  = qt * 64;

    const float* Qg = g_Q + (size_t)bh * NS * HD;
    const float* Kg = g_K + (size_t)bh * NS * HD;
    const float* Vg = g_V + (size_t)bh * NS * HD;

    // Load Q tile (64 x 128)
#pragma unroll
    for (int t = 0; t < 8; t++) {
        int idx = tid + t * 256;
        int r   = idx >> 5;
        int c4  = (idx & 31) << 2;
        *(float4*)&Qs[r * QS_STRIDE + c4] =
            *(const float4*)(Qg + (size_t)(q0 + r) * HD + c4);
    }

    // Roles:
    //  S-compute: (ty,tx) 16x16, each 4x4 score micro-tile
    //  softmax:   4 threads per score row (srow, lane4)
    //  O-update:  (qr,dc) 16x16, each 4 q-rows x 8 d-cols
    const int srow = tid >> 2, lane4 = tid & 3;
    const int qr   = tid >> 4, dc    = tid & 15;
    const int ty   = tid >> 4, tx    = tid & 15;

    float mrow = -1e30f, lrow = 0.f;
    float o[4][8];
#pragma unroll
    for (int i = 0; i < 4; i++)
#pragma unroll
        for (int j = 0; j < 8; j++) o[i][j] = 0.f;

    const float scl = 0.08838834764831845f;     // 1/sqrt(128)

    for (int jt = 0; jt <= qt; jt++) {
        const int k0 = jt * 64;
        __syncthreads();   // Qs ready (iter 0) / prev-iter consumers of Kt,Vs,Ssc done

        // Load K (transposed) and V tiles
#pragma unroll
        for (int t = 0; t < 8; t++) {
            int idx = tid + t * 256;
            int r   = idx >> 5;
            int c4  = (idx & 31) << 2;
            float4 kv = *(const float4*)(Kg + (size_t)(k0 + r) * HD + c4);
            Kt[(c4 + 0) * KT_STRIDE + r] = kv.x;
            Kt[(c4 + 1) * KT_STRIDE + r] = kv.y;
            Kt[(c4 + 2) * KT_STRIDE + r] = kv.z;
            Kt[(c4 + 3) * KT_STRIDE + r] = kv.w;
            *(float4*)&Vs[r * QS_STRIDE + c4] =
                *(const float4*)(Vg + (size_t)(k0 + r) * HD + c4);
        }
        __syncthreads();

        // S = (Q K^T) * scl, causal mask on diagonal tile
        {
            float accs[4][4];
#pragma unroll
            for (int i = 0; i < 4; i++)
#pragma unroll
                for (int j = 0; j < 4; j++) accs[i][j] = 0.f;

#pragma unroll 4
            for (int d = 0; d < HD; d++) {
                float4 kv = *(float4*)&Kt[d * KT_STRIDE + tx * 4];
#pragma unroll
                for (int i = 0; i < 4; i++) {
                    float qv = Qs[(ty * 4 + i) * QS_STRIDE + d];
                    accs[i][0] = fmaf(qv, kv.x, accs[i][0]);
                    accs[i][1] = fmaf(qv, kv.y, accs[i][1]);
                    accs[i][2] = fmaf(qv, kv.z, accs[i][2]);
                    accs[i][3] = fmaf(qv, kv.w, accs[i][3]);
                }
            }
            const bool diag = (jt == qt);
#pragma unroll
            for (int i = 0; i < 4; i++) {
                int gq = q0 + ty * 4 + i;
                float v0 = accs[i][0] * scl;
                float v1 = accs[i][1] * scl;
                float v2 = accs[i][2] * scl;
                float v3 = accs[i][3] * scl;
                if (diag) {
                    int gk = k0 + tx * 4;
                    if (gk + 0 > gq) v0 = -1e30f;
                    if (gk + 1 > gq) v1 = -1e30f;
                    if (gk + 2 > gq) v2 = -1e30f;
                    if (gk + 3 > gq) v3 = -1e30f;
                }
                float4 r; r.x = v0; r.y = v1; r.z = v2; r.w = v3;
                *(float4*)&Ssc[(ty * 4 + i) * SS_STRIDE + tx * 4] = r;
            }
        }
        __syncthreads();

        // Online softmax over this tile (4 threads per row)
        {
            float sv[16];
            float tmax = -1e30f;
            int base = srow * SS_STRIDE + lane4 * 16;
#pragma unroll
            for (int i = 0; i < 16; i++) {
                sv[i] = Ssc[base + i];
                tmax = fmaxf(tmax, sv[i]);
            }
            tmax = fmaxf(tmax, __shfl_xor_sync(0xffffffffu, tmax, 1));
            tmax = fmaxf(tmax, __shfl_xor_sync(0xffffffffu, tmax, 2));
            float mnew = fmaxf(mrow, tmax);
            float al   = __expf(mrow - mnew);
            float tsum = 0.f;
#pragma unroll
            for (int i = 0; i < 16; i++) {
                float p = __expf(sv[i] - mnew);
                Ssc[base + i] = p;
                tsum += p;
            }
            tsum += __shfl_xor_sync(0xffffffffu, tsum, 1);
            tsum += __shfl_xor_sync(0xffffffffu, tsum, 2);
            lrow = lrow * al + tsum;
            mrow = mnew;
            if (lane4 == 0) alpha_sh[srow] = al;
        }
        __syncthreads();

        // O = O*alpha + P @ V
        {
            float al0 = alpha_sh[qr * 4 + 0];
            float al1 = alpha_sh[qr * 4 + 1];
            float al2 = alpha_sh[qr * 4 + 2];
            float al3 = alpha_sh[qr * 4 + 3];
#pragma unroll
            for (int j = 0; j < 8; j++) {
                o[0][j] *= al0; o[1][j] *= al1; o[2][j] *= al2; o[3][j] *= al3;
            }
#pragma unroll 2
            for (int k = 0; k < 64; k++) {
                float p0 = Ssc[(qr * 4 + 0) * SS_STRIDE + k];
                float p1 = Ssc[(qr * 4 + 1) * SS_STRIDE + k];
                float p2 = Ssc[(qr * 4 + 2) * SS_STRIDE + k];
                float p3 = Ssc[(qr * 4 + 3) * SS_STRIDE + k];
                float4 v0 = *(float4*)&Vs[k * QS_STRIDE + dc * 8];
                float4 v1 = *(float4*)&Vs[k * QS_STRIDE + dc * 8 + 4];
                float vv[8] = {v0.x, v0.y, v0.z, v0.w, v1.x, v1.y, v1.z, v1.w};
#pragma unroll
                for (int j = 0; j < 8; j++) {
                    o[0][j] = fmaf(p0, vv[j], o[0][j]);
                    o[1][j] = fmaf(p1, vv[j], o[1][j]);
                    o[2][j] = fmaf(p2, vv[j], o[2][j]);
                    o[3][j] = fmaf(p3, vv[j], o[3][j]);
                }
            }
        }
    }

    if (lane4 == 0) l_sh[srow] = lrow;
    __syncthreads();

    // Write O tile: g_O[b][s][head*128 + d]
    const int b    = bh >> 4;
    const int head = bh & 15;
    float* Og = g_O + (size_t)b * NS * NHID + (size_t)head * HD;
#pragma unroll
    for (int i = 0; i < 4; i++) {
        int s = q0 + qr * 4 + i;
        float inv = 1.f / l_sh[qr * 4 + i];
        float4 r0, r1;
        r0.x = o[i][0] * inv; r0.y = o[i][1] * inv;
        r0.z = o[i][2] * inv; r0.w = o[i][3] * inv;
        r1.x = o[i][4] * inv; r1.y = o[i][5] * inv;
        r1.z = o[i][6] * inv; r1.w = o[i][7] * inv;
        *(float4*)&Og[(size_t)s * NHID + dc * 8]     = r0;
        *(float4*)&Og[(size_t)s * NHID + dc * 8 + 4] = r1;
    }
}

// ---------------------------------------------------------------------------
extern "C" void kernel_launch(void* const* d_in, const int* in_sizes, int n_in,
                              void* d_out, int out_size)
{
    const float* x    = (const float*)d_in[0];
    const float* Wqkv = (const float*)d_in[1];
    const float* bqkv = (const float*)d_in[2];
    const float* Wo   = (const float*)d_in[3];
    const float* bo   = (const float*)d_in[4];
    float* out = (float*)d_out;

    // Idempotent, non-stream API; persists across graph capture.
    cudaFuncSetAttribute(attn_kernel, cudaFuncAttributeMaxDynamicSharedMemorySize,
                         (int)ATTN_SMEM);

    // 1) QKV projection + bias, scatter to per-head Q/K/V
    sgemm_kernel<0><<<dim3(N3 / 128, (NB * NS) / 128), 256>>>(
        x, Wqkv, bqkv, nullptr, N3, NHID);

    // 2) Causal attention per (b, head), 64-query tiles
    attn_kernel<<<dim3(NS / 64, NB * NHEADS), 256, ATTN_SMEM>>>();

    // 3) Output projection + bias
    sgemm_kernel<1><<<dim3(NHID / 128, (NB * NS) / 128), 256>>>(
        nullptr, Wo, bo, out, NHID, NHID);
}

// round 8
// speedup vs baseline: 1.6207x; 1.6207x over previous
#include <cuda_runtime.h>
#include <cuda_bf16.h>
#include <cstdint>

#define NB 2
#define NS 2048
#define NHID 2048
#define NHEADS 16
#define HD 128
#define N3 6144
#define M_TOT 4096   // NB*NS

// ---------------- scratch (__device__ globals per allocation rules) --------
__device__ float g_Q[NB*NHEADS*NS*HD];
__device__ float g_K[NB*NHEADS*NS*HD];
__device__ float g_V[NB*NHEADS*NS*HD];
__device__ float g_O[NB*NS*NHID];

__device__ __align__(16) __nv_bfloat16 g_xh[M_TOT*NHID];
__device__ __align__(16) __nv_bfloat16 g_xl[M_TOT*NHID];
__device__ __align__(16) __nv_bfloat16 g_Wqh[N3*NHID];    // Wqkv^T [6144][2048]
__device__ __align__(16) __nv_bfloat16 g_Wql[N3*NHID];
__device__ __align__(16) __nv_bfloat16 g_Woh[NHID*NHID];  // Wo^T [2048][2048]
__device__ __align__(16) __nv_bfloat16 g_Wol[NHID*NHID];
__device__ __align__(16) __nv_bfloat16 g_Oh[M_TOT*NHID];
__device__ __align__(16) __nv_bfloat16 g_Ol[M_TOT*NHID];

// ---------------- helpers --------------------------------------------------
__device__ __forceinline__ uint32_t smem_u32(const void* p) {
    uint32_t a;
    asm("{ .reg .u64 t; cvta.to.shared.u64 t, %1; cvt.u32.u64 %0, t; }" : "=r"(a) : "l"(p));
    return a;
}
#define CP_ASYNC16(s, g) asm volatile("cp.async.cg.shared.global [%0], [%1], 16;" :: "r"(s), "l"(g) : "memory")
#define CP_COMMIT()      asm volatile("cp.async.commit_group;" ::: "memory")
#define CP_WAIT(n)       asm volatile("cp.async.wait_group %0;" :: "n"(n) : "memory")

__device__ __forceinline__ void mma_bf16(float* d, const uint32_t* a, const uint32_t* b) {
    asm volatile(
        "mma.sync.aligned.m16n8k16.row.col.f32.bf16.bf16.f32 "
        "{%0,%1,%2,%3}, {%4,%5,%6,%7}, {%8,%9}, {%0,%1,%2,%3};"
        : "+f"(d[0]), "+f"(d[1]), "+f"(d[2]), "+f"(d[3])
        : "r"(a[0]), "r"(a[1]), "r"(a[2]), "r"(a[3]), "r"(b[0]), "r"(b[1]));
}

// ---------------------------------------------------------------------------
// hi/lo bf16 split kernels
// ---------------------------------------------------------------------------
template<int WHICH>  // 0: x -> g_xh/g_xl ; 1: g_O -> g_Oh/g_Ol
__global__ __launch_bounds__(256)
void split_rm_kernel(const float* __restrict__ src_in)
{
    const float* src = (WHICH == 0) ? src_in : (const float*)g_O;
    __nv_bfloat16* dh = (WHICH == 0) ? g_xh : g_Oh;
    __nv_bfloat16* dl = (WHICH == 0) ? g_xl : g_Ol;
    size_t i = ((size_t)blockIdx.x * 256 + threadIdx.x) * 4;
    float4 v = *(const float4*)(src + i);
    __nv_bfloat16 h0 = __float2bfloat16(v.x), h1 = __float2bfloat16(v.y);
    __nv_bfloat16 h2 = __float2bfloat16(v.z), h3 = __float2bfloat16(v.w);
    __nv_bfloat162 hh0; hh0.x = h0; hh0.y = h1;
    __nv_bfloat162 hh1; hh1.x = h2; hh1.y = h3;
    __nv_bfloat162 ll0, ll1;
    ll0.x = __float2bfloat16(v.x - __bfloat162float(h0));
    ll0.y = __float2bfloat16(v.y - __bfloat162float(h1));
    ll1.x = __float2bfloat16(v.z - __bfloat162float(h2));
    ll1.y = __float2bfloat16(v.w - __bfloat162float(h3));
    *(__nv_bfloat162*)(dh + i)     = hh0;
    *(__nv_bfloat162*)(dh + i + 2) = hh1;
    *(__nv_bfloat162*)(dl + i)     = ll0;
    *(__nv_bfloat162*)(dl + i + 2) = ll1;
}

template<int WHICH>  // 0: Wqkv [2048][6144] -> g_Wqh/l [6144][2048]; 1: Wo -> g_Woh/l
__global__ __launch_bounds__(256)
void split_tr_kernel(const float* __restrict__ W)
{
    constexpr int N = (WHICH == 0) ? N3 : NHID;
    __nv_bfloat16* dh = (WHICH == 0) ? g_Wqh : g_Woh;
    __nv_bfloat16* dl = (WHICH == 0) ? g_Wql : g_Wol;
    __shared__ float t[32][33];
    int k0 = blockIdx.y * 32, n0 = blockIdx.x * 32;
    int tx = threadIdx.x, ty = threadIdx.y;
#pragma unroll
    for (int i = 0; i < 4; i++)
        t[ty + i * 8][tx] = W[(size_t)(k0 + ty + i * 8) * N + n0 + tx];
    __syncthreads();
#pragma unroll
    for (int i = 0; i < 4; i++) {
        float v = t[tx][ty + i * 8];
        __nv_bfloat16 h = __float2bfloat16(v);
        size_t o = (size_t)(n0 + ty + i * 8) * NHID + k0 + tx;
        dh[o] = h;
        dl[o] = __float2bfloat16(v - __bfloat162float(h));
    }
}

// ---------------------------------------------------------------------------
// Split-bf16 HMMA GEMM: D[M,N] = A @ B^T + bias
//   A: [M, 2048] K-major hi/lo; B: [N, 2048] K-major hi/lo
//   D = Ah*Bh + Ah*Bl + Al*Bh accumulated in fp32 fragments (3 passes)
// CTA tile 128x128, BK=32, 8 warps (each 64x32), cp.async double buffer.
// SMEM tile layout: [128 rows][40 halves] per array (pad -> conflict-free).
// MODE 0: +bqkv, scatter -> g_Q/g_K/g_V ; MODE 1: +bo -> C
// ---------------------------------------------------------------------------
#define TILE_HALVES (128 * 40)                 // one array
#define STAGE_HALVES (4 * TILE_HALVES)         // Ah,Al,Bh,Bl
#define GEMM_SMEM (2 * STAGE_HALVES * 2)       // bytes (81920)

template<int MODE>
__global__ __launch_bounds__(256, 2)
void gemm_mma(const float* __restrict__ bias, float* __restrict__ C)
{
    constexpr int Kdim = NHID;
    constexpr int NT = Kdim / 32;              // 64 K-stages

    extern __shared__ char smem[];
    const uint32_t sbase = smem_u32(smem);
    uint32_t* S32 = (uint32_t*)smem;

    const int tid  = threadIdx.x;
    const int wid  = tid >> 5;
    const int lane = tid & 31;
    const int mBase = blockIdx.y * 128;
    const int nBase = blockIdx.x * 128;
    const int wm = (wid >> 2) * 64;            // warp M offset (0/64)
    const int wn = (wid & 3) * 32;             // warp N offset (0/32/64/96)

    const __nv_bfloat16* Ah = (MODE == 0) ? g_xh : g_Oh;
    const __nv_bfloat16* Al = (MODE == 0) ? g_xl : g_Ol;
    const __nv_bfloat16* Bh = (MODE == 0) ? g_Wqh : g_Woh;
    const __nv_bfloat16* Bl = (MODE == 0) ? g_Wql : g_Wol;

    const __nv_bfloat16* srcs[4] = {
        Ah + (size_t)mBase * Kdim, Al + (size_t)mBase * Kdim,
        Bh + (size_t)nBase * Kdim, Bl + (size_t)nBase * Kdim };

    // accumulators: [mb 0..3][nb 0..3][4]
    float acc[4][4][4];
#pragma unroll
    for (int i = 0; i < 4; i++)
#pragma unroll
        for (int j = 0; j < 4; j++)
#pragma unroll
            for (int q = 0; q < 4; q++) acc[i][j][q] = 0.f;

    // stage loader: 2048 x 16B chunks, 8 per thread
    auto load_stage = [&](int t, int stage) {
        const int k0 = t * 32;
#pragma unroll
        for (int i = 0; i < 8; i++) {
            int idx = tid + i * 256;
            int arr = idx >> 9;
            int rem = idx & 511;
            int row = rem >> 2;
            int q   = rem & 3;                  // 16B chunk within 64B row span
            uint32_t saddr = sbase +
                (uint32_t)((stage * 4 + arr) * TILE_HALVES + row * 40) * 2 + q * 16;
            const __nv_bfloat16* g = srcs[arr] + (size_t)row * Kdim + k0 + q * 8;
            CP_ASYNC16(saddr, (const void*)g);
        }
    };

    load_stage(0, 0);
    CP_COMMIT();

    const int fr = lane >> 2;                  // 0..7
    const int fq = lane & 3;                   // 0..3

    for (int t = 0; t < NT; ++t) {
        const int stage = t & 1;
        if (t + 1 < NT) {
            load_stage(t + 1, stage ^ 1);
            CP_COMMIT();
            CP_WAIT(1);
        } else {
            CP_WAIT(0);
        }
        __syncthreads();

        // base u32 indices of the 4 arrays for this stage (u32 row stride = 20)
        const int b0 = (stage * 4) * (TILE_HALVES / 2);
#pragma unroll
        for (int pass = 0; pass < 3; pass++) {
            const int Abase = b0 + ((pass == 2) ? 1 : 0) * (TILE_HALVES / 2);
            const int Bbase = b0 + (2 + ((pass == 1) ? 1 : 0)) * (TILE_HALVES / 2);
#pragma unroll
            for (int kc = 0; kc < 2; kc++) {
                const int colu = kc * 8 + fq;  // u32 column (0..15 of 20)
                uint32_t afr[4][4], bfr[4][2];
#pragma unroll
                for (int mb = 0; mb < 4; mb++) {
                    int r0 = wm + mb * 16 + fr;
                    afr[mb][0] = S32[Abase + r0 * 20 + colu];
                    afr[mb][1] = S32[Abase + (r0 + 8) * 20 + colu];
                    afr[mb][2] = S32[Abase + r0 * 20 + colu + 4];
                    afr[mb][3] = S32[Abase + (r0 + 8) * 20 + colu + 4];
                }
#pragma unroll
                for (int nb = 0; nb < 4; nb++) {
                    int rn = wn + nb * 8 + fr;
                    bfr[nb][0] = S32[Bbase + rn * 20 + colu];
                    bfr[nb][1] = S32[Bbase + rn * 20 + colu + 4];
                }
#pragma unroll
                for (int mb = 0; mb < 4; mb++)
#pragma unroll
                    for (int nb = 0; nb < 4; nb++)
                        mma_bf16(acc[mb][nb], afr[mb], bfr[nb]);
            }
        }
        __syncthreads();
    }

    // Epilogue: D fragment -> +bias -> store (float2 per pair)
#pragma unroll
    for (int mb = 0; mb < 4; mb++) {
#pragma unroll
        for (int nb = 0; nb < 4; nb++) {
            int n = nBase + wn + nb * 8 + 2 * fq;
            float bx = bias[n], by = bias[n + 1];
#pragma unroll
            for (int half = 0; half < 2; half++) {
                int m = mBase + wm + mb * 16 + fr + half * 8;
                float2 r;
                r.x = acc[mb][nb][half * 2 + 0] + bx;
                r.y = acc[mb][nb][half * 2 + 1] + by;
                if (MODE == 0) {
                    int sel  = n >> 11;          // 0:Q 1:K 2:V
                    int rem  = n & 2047;
                    int head = rem >> 7;
                    int d    = rem & 127;
                    int b    = m >> 11;
                    int s    = m & 2047;
                    float* dst = (sel == 0) ? g_Q : ((sel == 1) ? g_K : g_V);
                    *(float2*)&dst[(size_t)((b * NHEADS + head) * NS + s) * HD + d] = r;
                } else {
                    *(float2*)&C[(size_t)m * NHID + n] = r;
                }
            }
        }
    }
}

// ---------------------------------------------------------------------------
// Causal flash attention, fp32 SIMT (unchanged from passing R4 kernel).
// ---------------------------------------------------------------------------
#define QS_STRIDE 132
#define KT_STRIDE 68
#define SS_STRIDE 68
#define ATTN_SMEM ((64*QS_STRIDE + 128*KT_STRIDE + 64*QS_STRIDE + 64*SS_STRIDE + 128) * sizeof(float))

__global__ __launch_bounds__(256)
void attn_kernel()
{
    extern __shared__ float sm[];
    float* Qs      = sm;
    float* Kt      = Qs + 64 * QS_STRIDE;
    float* Vs      = Kt + 128 * KT_STRIDE;
    float* Ssc     = Vs + 64 * QS_STRIDE;
    float* alpha_sh = Ssc + 64 * SS_STRIDE;
    float* l_sh     = alpha_sh + 64;

    const int tid = threadIdx.x;
    const int bh  = blockIdx.y;
    const int qt  = blockIdx.x;
    const int q0  = qt * 64;

    const float* Qg = g_Q + (size_t)bh * NS * HD;
    const float* Kg = g_K + (size_t)bh * NS * HD;
    const float* Vg = g_V + (size_t)bh * NS * HD;

#pragma unroll
    for (int t = 0; t < 8; t++) {
        int idx = tid + t * 256;
        int r   = idx >> 5;
        int c4  = (idx & 31) << 2;
        *(float4*)&Qs[r * QS_STRIDE + c4] =
            *(const float4*)(Qg + (size_t)(q0 + r) * HD + c4);
    }

    const int srow = tid >> 2, lane4 = tid & 3;
    const int qr   = tid >> 4, dc    = tid & 15;
    const int ty   = tid >> 4, tx    = tid & 15;

    float mrow = -1e30f, lrow = 0.f;
    float o[4][8];
#pragma unroll
    for (int i = 0; i < 4; i++)
#pragma unroll
        for (int j = 0; j < 8; j++) o[i][j] = 0.f;

    const float scl = 0.08838834764831845f;

    for (int jt = 0; jt <= qt; jt++) {
        const int k0 = jt * 64;
        __syncthreads();

#pragma unroll
        for (int t = 0; t < 8; t++) {
            int idx = tid + t * 256;
            int r   = idx >> 5;
            int c4  = (idx & 31) << 2;
            float4 kv = *(const float4*)(Kg + (size_t)(k0 + r) * HD + c4);
            Kt[(c4 + 0) * KT_STRIDE + r] = kv.x;
            Kt[(c4 + 1) * KT_STRIDE + r] = kv.y;
            Kt[(c4 + 2) * KT_STRIDE + r] = kv.z;
            Kt[(c4 + 3) * KT_STRIDE + r] = kv.w;
            *(float4*)&Vs[r * QS_STRIDE + c4] =
                *(const float4*)(Vg + (size_t)(k0 + r) * HD + c4);
        }
        __syncthreads();

        {
            float accs[4][4];
#pragma unroll
            for (int i = 0; i < 4; i++)
#pragma unroll
                for (int j = 0; j < 4; j++) accs[i][j] = 0.f;

#pragma unroll 4
            for (int d = 0; d < HD; d++) {
                float4 kv = *(float4*)&Kt[d * KT_STRIDE + tx * 4];
#pragma unroll
                for (int i = 0; i < 4; i++) {
                    float qv = Qs[(ty * 4 + i) * QS_STRIDE + d];
                    accs[i][0] = fmaf(qv, kv.x, accs[i][0]);
                    accs[i][1] = fmaf(qv, kv.y, accs[i][1]);
                    accs[i][2] = fmaf(qv, kv.z, accs[i][2]);
                    accs[i][3] = fmaf(qv, kv.w, accs[i][3]);
                }
            }
            const bool diag = (jt == qt);
#pragma unroll
            for (int i = 0; i < 4; i++) {
                int gq = q0 + ty * 4 + i;
                float v0 = accs[i][0] * scl;
                float v1 = accs[i][1] * scl;
                float v2 = accs[i][2] * scl;
                float v3 = accs[i][3] * scl;
                if (diag) {
                    int gk = k0 + tx * 4;
                    if (gk + 0 > gq) v0 = -1e30f;
                    if (gk + 1 > gq) v1 = -1e30f;
                    if (gk + 2 > gq) v2 = -1e30f;
                    if (gk + 3 > gq) v3 = -1e30f;
                }
                float4 r; r.x = v0; r.y = v1; r.z = v2; r.w = v3;
                *(float4*)&Ssc[(ty * 4 + i) * SS_STRIDE + tx * 4] = r;
            }
        }
        __syncthreads();

        {
            float sv[16];
            float tmax = -1e30f;
            int base = srow * SS_STRIDE + lane4 * 16;
#pragma unroll
            for (int i = 0; i < 16; i++) {
                sv[i] = Ssc[base + i];
                tmax = fmaxf(tmax, sv[i]);
            }
            tmax = fmaxf(tmax, __shfl_xor_sync(0xffffffffu, tmax, 1));
            tmax = fmaxf(tmax, __shfl_xor_sync(0xffffffffu, tmax, 2));
            float mnew = fmaxf(mrow, tmax);
            float al   = __expf(mrow - mnew);
            float tsum = 0.f;
#pragma unroll
            for (int i = 0; i < 16; i++) {
                float p = __expf(sv[i] - mnew);
                Ssc[base + i] = p;
                tsum += p;
            }
            tsum += __shfl_xor_sync(0xffffffffu, tsum, 1);
            tsum += __shfl_xor_sync(0xffffffffu, tsum, 2);
            lrow = lrow * al + tsum;
            mrow = mnew;
            if (lane4 == 0) alpha_sh[srow] = al;
        }
        __syncthreads();

        {
            float al0 = alpha_sh[qr * 4 + 0];
            float al1 = alpha_sh[qr * 4 + 1];
            float al2 = alpha_sh[qr * 4 + 2];
            float al3 = alpha_sh[qr * 4 + 3];
#pragma unroll
            for (int j = 0; j < 8; j++) {
                o[0][j] *= al0; o[1][j] *= al1; o[2][j] *= al2; o[3][j] *= al3;
            }
#pragma unroll 2
            for (int k = 0; k < 64; k++) {
                float p0 = Ssc[(qr * 4 + 0) * SS_STRIDE + k];
                float p1 = Ssc[(qr * 4 + 1) * SS_STRIDE + k];
                float p2 = Ssc[(qr * 4 + 2) * SS_STRIDE + k];
                float p3 = Ssc[(qr * 4 + 3) * SS_STRIDE + k];
                float4 v0 = *(float4*)&Vs[k * QS_STRIDE + dc * 8];
                float4 v1 = *(float4*)&Vs[k * QS_STRIDE + dc * 8 + 4];
                float vv[8] = {v0.x, v0.y, v0.z, v0.w, v1.x, v1.y, v1.z, v1.w};
#pragma unroll
                for (int j = 0; j < 8; j++) {
                    o[0][j] = fmaf(p0, vv[j], o[0][j]);
                    o[1][j] = fmaf(p1, vv[j], o[1][j]);
                    o[2][j] = fmaf(p2, vv[j], o[2][j]);
                    o[3][j] = fmaf(p3, vv[j], o[3][j]);
                }
            }
        }
    }

    if (lane4 == 0) l_sh[srow] = lrow;
    __syncthreads();

    const int b    = bh >> 4;
    const int head = bh & 15;
    float* Og = g_O + (size_t)b * NS * NHID + (size_t)head * HD;
#pragma unroll
    for (int i = 0; i < 4; i++) {
        int s = q0 + qr * 4 + i;
        float inv = 1.f / l_sh[qr * 4 + i];
        float4 r0, r1;
        r0.x = o[i][0] * inv; r0.y = o[i][1] * inv;
        r0.z = o[i][2] * inv; r0.w = o[i][3] * inv;
        r1.x = o[i][4] * inv; r1.y = o[i][5] * inv;
        r1.z = o[i][6] * inv; r1.w = o[i][7] * inv;
        *(float4*)&Og[(size_t)s * NHID + dc * 8]     = r0;
        *(float4*)&Og[(size_t)s * NHID + dc * 8 + 4] = r1;
    }
}

// ---------------------------------------------------------------------------
extern "C" void kernel_launch(void* const* d_in, const int* in_sizes, int n_in,
                              void* d_out, int out_size)
{
    const float* x    = (const float*)d_in[0];
    const float* Wqkv = (const float*)d_in[1];
    const float* bqkv = (const float*)d_in[2];
    const float* Wo   = (const float*)d_in[3];
    const float* bo   = (const float*)d_in[4];
    float* out = (float*)d_out;

    cudaFuncSetAttribute(attn_kernel, cudaFuncAttributeMaxDynamicSharedMemorySize,
                         (int)ATTN_SMEM);
    cudaFuncSetAttribute(gemm_mma<0>, cudaFuncAttributeMaxDynamicSharedMemorySize,
                         (int)GEMM_SMEM);
    cudaFuncSetAttribute(gemm_mma<1>, cudaFuncAttributeMaxDynamicSharedMemorySize,
                         (int)GEMM_SMEM);

    // hi/lo splits (+ weight transposes to [N][K] K-major)
    split_rm_kernel<0><<<(M_TOT * NHID) / 1024, 256>>>(x);
    split_tr_kernel<0><<<dim3(N3 / 32, NHID / 32), dim3(32, 8)>>>(Wqkv);
    split_tr_kernel<1><<<dim3(NHID / 32, NHID / 32), dim3(32, 8)>>>(Wo);

    // 1) QKV projection on HMMA tensor cores, scatter to g_Q/g_K/g_V
    gemm_mma<0><<<dim3(N3 / 128, M_TOT / 128), 256, GEMM_SMEM>>>(bqkv, nullptr);

    // 2) causal attention
    attn_kernel<<<dim3(NS / 64, NB * NHEADS), 256, ATTN_SMEM>>>();

    // 3) output projection on HMMA tensor cores
    split_rm_kernel<1><<<(M_TOT * NHID) / 1024, 256>>>(nullptr);
    gemm_mma<1><<<dim3(NHID / 128, M_TOT / 128), 256, GEMM_SMEM>>>(bo, out);
}

// round 9
// speedup vs baseline: 2.4953x; 1.5397x over previous
#include <cuda_runtime.h>
#include <cuda_bf16.h>
#include <cstdint>

#define NB 2
#define NS 2048
#define NHID 2048
#define NHEADS 16
#define HD 128
#define N3 6144
#define M_TOT 4096   // NB*NS

// ---------------- scratch (__device__ globals per allocation rules) --------
__device__ __align__(16) __nv_bfloat16 g_xh[M_TOT*NHID];
__device__ __align__(16) __nv_bfloat16 g_xl[M_TOT*NHID];
__device__ __align__(16) __nv_bfloat16 g_Wqh[N3*NHID];    // Wqkv^T [6144][2048]
__device__ __align__(16) __nv_bfloat16 g_Wql[N3*NHID];
__device__ __align__(16) __nv_bfloat16 g_Woh[NHID*NHID];  // Wo^T [2048][2048]
__device__ __align__(16) __nv_bfloat16 g_Wol[NHID*NHID];
__device__ __align__(16) __nv_bfloat16 g_Oh[M_TOT*NHID];
__device__ __align__(16) __nv_bfloat16 g_Ol[M_TOT*NHID];
// per-head Q/K/V hi/lo: [bh][2048][128]
__device__ __align__(16) __nv_bfloat16 g_Qh[NB*NHEADS*NS*HD];
__device__ __align__(16) __nv_bfloat16 g_Ql[NB*NHEADS*NS*HD];
__device__ __align__(16) __nv_bfloat16 g_Kh[NB*NHEADS*NS*HD];
__device__ __align__(16) __nv_bfloat16 g_Kl[NB*NHEADS*NS*HD];
__device__ __align__(16) __nv_bfloat16 g_Vh[NB*NHEADS*NS*HD];
__device__ __align__(16) __nv_bfloat16 g_Vl[NB*NHEADS*NS*HD];

// ---------------- helpers --------------------------------------------------
__device__ __forceinline__ uint32_t smem_u32(const void* p) {
    uint32_t a;
    asm("{ .reg .u64 t; cvta.to.shared.u64 t, %1; cvt.u32.u64 %0, t; }" : "=r"(a) : "l"(p));
    return a;
}
#define CP_ASYNC16(s, g) asm volatile("cp.async.cg.shared.global [%0], [%1], 16;" :: "r"(s), "l"(g) : "memory")
#define CP_COMMIT()      asm volatile("cp.async.commit_group;" ::: "memory")
#define CP_WAIT(n)       asm volatile("cp.async.wait_group %0;" :: "n"(n) : "memory")

__device__ __forceinline__ void mma_bf16(float* d, const uint32_t* a, const uint32_t* b) {
    asm volatile(
        "mma.sync.aligned.m16n8k16.row.col.f32.bf16.bf16.f32 "
        "{%0,%1,%2,%3}, {%4,%5,%6,%7}, {%8,%9}, {%0,%1,%2,%3};"
        : "+f"(d[0]), "+f"(d[1]), "+f"(d[2]), "+f"(d[3])
        : "r"(a[0]), "r"(a[1]), "r"(a[2]), "r"(a[3]), "r"(b[0]), "r"(b[1]));
}

// pack (x -> low half, y -> high half) as bf16x2 hi + residual lo
__device__ __forceinline__ void pack_hl(float x, float y, uint32_t& h, uint32_t& l) {
    __nv_bfloat162 hh = __floats2bfloat162_rn(x, y);
    float rx = x - __bfloat162float(hh.x);
    float ry = y - __bfloat162float(hh.y);
    __nv_bfloat162 ll = __floats2bfloat162_rn(rx, ry);
    h = *(uint32_t*)&hh;
    l = *(uint32_t*)&ll;
}

// ---------------------------------------------------------------------------
// hi/lo bf16 split kernels
// ---------------------------------------------------------------------------
__global__ __launch_bounds__(256)
void split_x_kernel(const float* __restrict__ src)
{
    size_t i = ((size_t)blockIdx.x * 256 + threadIdx.x) * 4;
    float4 v = *(const float4*)(src + i);
    uint32_t h0, l0, h1, l1;
    pack_hl(v.x, v.y, h0, l0);
    pack_hl(v.z, v.w, h1, l1);
    *(uint32_t*)&g_xh[i]     = h0;
    *(uint32_t*)&g_xh[i + 2] = h1;
    *(uint32_t*)&g_xl[i]     = l0;
    *(uint32_t*)&g_xl[i + 2] = l1;
}

template<int WHICH>  // 0: Wqkv [2048][6144] -> g_Wqh/l [6144][2048]; 1: Wo -> g_Woh/l
__global__ __launch_bounds__(256)
void split_tr_kernel(const float* __restrict__ W)
{
    constexpr int N = (WHICH == 0) ? N3 : NHID;
    __nv_bfloat16* dh = (WHICH == 0) ? g_Wqh : g_Woh;
    __nv_bfloat16* dl = (WHICH == 0) ? g_Wql : g_Wol;
    __shared__ float t[32][33];
    int k0 = blockIdx.y * 32, n0 = blockIdx.x * 32;
    int tx = threadIdx.x, ty = threadIdx.y;
#pragma unroll
    for (int i = 0; i < 4; i++)
        t[ty + i * 8][tx] = W[(size_t)(k0 + ty + i * 8) * N + n0 + tx];
    __syncthreads();
#pragma unroll
    for (int i = 0; i < 4; i++) {
        float v = t[tx][ty + i * 8];
        __nv_bfloat16 h = __float2bfloat16(v);
        size_t o = (size_t)(n0 + ty + i * 8) * NHID + k0 + tx;
        dh[o] = h;
        dl[o] = __float2bfloat16(v - __bfloat162float(h));
    }
}

// ---------------------------------------------------------------------------
// Split-bf16 HMMA GEMM: D[M,N] = A @ B^T + bias   (3-pass error compensation)
// MODE 0: +bqkv, scatter hi/lo bf16 -> g_{Q,K,V}{h,l} ; MODE 1: +bo -> C fp32
// ---------------------------------------------------------------------------
#define TILE_HALVES (128 * 40)
#define STAGE_HALVES (4 * TILE_HALVES)
#define GEMM_SMEM (2 * STAGE_HALVES * 2)

template<int MODE>
__global__ __launch_bounds__(256, 2)
void gemm_mma(const float* __restrict__ bias, float* __restrict__ C)
{
    constexpr int Kdim = NHID;
    constexpr int NT = Kdim / 32;

    extern __shared__ char smem[];
    const uint32_t sbase = smem_u32(smem);
    uint32_t* S32 = (uint32_t*)smem;

    const int tid  = threadIdx.x;
    const int wid  = tid >> 5;
    const int lane = tid & 31;
    const int mBase = blockIdx.y * 128;
    const int nBase = blockIdx.x * 128;
    const int wm = (wid >> 2) * 64;
    const int wn = (wid & 3) * 32;

    const __nv_bfloat16* Ah = (MODE == 0) ? g_xh : g_Oh;
    const __nv_bfloat16* Al = (MODE == 0) ? g_xl : g_Ol;
    const __nv_bfloat16* Bh = (MODE == 0) ? g_Wqh : g_Woh;
    const __nv_bfloat16* Bl = (MODE == 0) ? g_Wql : g_Wol;

    const __nv_bfloat16* srcs[4] = {
        Ah + (size_t)mBase * Kdim, Al + (size_t)mBase * Kdim,
        Bh + (size_t)nBase * Kdim, Bl + (size_t)nBase * Kdim };

    float acc[4][4][4];
#pragma unroll
    for (int i = 0; i < 4; i++)
#pragma unroll
        for (int j = 0; j < 4; j++)
#pragma unroll
            for (int q = 0; q < 4; q++) acc[i][j][q] = 0.f;

    auto load_stage = [&](int t, int stage) {
        const int k0 = t * 32;
#pragma unroll
        for (int i = 0; i < 8; i++) {
            int idx = tid + i * 256;
            int arr = idx >> 9;
            int rem = idx & 511;
            int row = rem >> 2;
            int q   = rem & 3;
            uint32_t saddr = sbase +
                (uint32_t)((stage * 4 + arr) * TILE_HALVES + row * 40) * 2 + q * 16;
            const __nv_bfloat16* g = srcs[arr] + (size_t)row * Kdim + k0 + q * 8;
            CP_ASYNC16(saddr, (const void*)g);
        }
    };

    load_stage(0, 0);
    CP_COMMIT();

    const int fr = lane >> 2;
    const int fq = lane & 3;

    for (int t = 0; t < NT; ++t) {
        const int stage = t & 1;
        if (t + 1 < NT) {
            load_stage(t + 1, stage ^ 1);
            CP_COMMIT();
            CP_WAIT(1);
        } else {
            CP_WAIT(0);
        }
        __syncthreads();

        const int b0 = (stage * 4) * (TILE_HALVES / 2);
#pragma unroll
        for (int pass = 0; pass < 3; pass++) {
            const int Abase = b0 + ((pass == 2) ? 1 : 0) * (TILE_HALVES / 2);
            const int Bbase = b0 + (2 + ((pass == 1) ? 1 : 0)) * (TILE_HALVES / 2);
#pragma unroll
            for (int kc = 0; kc < 2; kc++) {
                const int colu = kc * 8 + fq;
                uint32_t afr[4][4], bfr[4][2];
#pragma unroll
                for (int mb = 0; mb < 4; mb++) {
                    int r0 = wm + mb * 16 + fr;
                    afr[mb][0] = S32[Abase + r0 * 20 + colu];
                    afr[mb][1] = S32[Abase + (r0 + 8) * 20 + colu];
                    afr[mb][2] = S32[Abase + r0 * 20 + colu + 4];
                    afr[mb][3] = S32[Abase + (r0 + 8) * 20 + colu + 4];
                }
#pragma unroll
                for (int nb = 0; nb < 4; nb++) {
                    int rn = wn + nb * 8 + fr;
                    bfr[nb][0] = S32[Bbase + rn * 20 + colu];
                    bfr[nb][1] = S32[Bbase + rn * 20 + colu + 4];
                }
#pragma unroll
                for (int mb = 0; mb < 4; mb++)
#pragma unroll
                    for (int nb = 0; nb < 4; nb++)
                        mma_bf16(acc[mb][nb], afr[mb], bfr[nb]);
            }
        }
        __syncthreads();
    }

    // Epilogue
#pragma unroll
    for (int mb = 0; mb < 4; mb++) {
#pragma unroll
        for (int nb = 0; nb < 4; nb++) {
            int n = nBase + wn + nb * 8 + 2 * fq;
            float bx = bias[n], by = bias[n + 1];
#pragma unroll
            for (int half = 0; half < 2; half++) {
                int m = mBase + wm + mb * 16 + fr + half * 8;
                float rx = acc[mb][nb][half * 2 + 0] + bx;
                float ry = acc[mb][nb][half * 2 + 1] + by;
                if (MODE == 0) {
                    int sel  = n >> 11;
                    int rem  = n & 2047;
                    int head = rem >> 7;
                    int d    = rem & 127;
                    int b    = m >> 11;
                    int s    = m & 2047;
                    __nv_bfloat16* dh = (sel == 0) ? g_Qh : ((sel == 1) ? g_Kh : g_Vh);
                    __nv_bfloat16* dl = (sel == 0) ? g_Ql : ((sel == 1) ? g_Kl : g_Vl);
                    size_t idx = (size_t)((b * NHEADS + head) * NS + s) * HD + d;
                    uint32_t h, l;
                    pack_hl(rx, ry, h, l);
                    *(uint32_t*)&dh[idx] = h;
                    *(uint32_t*)&dl[idx] = l;
                } else {
                    float2 r; r.x = rx; r.y = ry;
                    *(float2*)&C[(size_t)m * NHID + n] = r;
                }
            }
        }
    }
}

// ---------------------------------------------------------------------------
// Causal flash attention on HMMA, split-bf16 3-pass for QK^T and PV.
// Grid (16 q-tiles, 32 bh), 256 threads = 8 warps, each warp owns 16 q-rows.
// BQ=128, BK=64. Softmax entirely in registers (+2 quad shuffles).
// SMEM u32 layout:
//   Qh:0  Ql:8704  Kh:17408  Kl:21760  Vth:26112  Vtl:30720   (total 141312 B)
//   Q/K tiles: [rows][136 halves] (stride 68 u32); Vt: [128 d][36 u32 key-pairs]
// ---------------------------------------------------------------------------
#define AQH 0
#define AQL 8704
#define AKH 17408
#define AKL 21760
#define AVH 26112
#define AVL 30720
#define ATTN_SMEM 141312

__global__ __launch_bounds__(256)
void attn_mma()
{
    extern __shared__ char smem[];
    const uint32_t sbase = smem_u32(smem);
    uint32_t* S32 = (uint32_t*)smem;

    const int tid = threadIdx.x;
    const int wid = tid >> 5;
    const int lane = tid & 31;
    const int fr = lane >> 2;
    const int fq = lane & 3;
    const int bh = blockIdx.y;
    const int qt = blockIdx.x;
    const int q0 = qt * 128;

    const size_t hoff = (size_t)bh * NS * HD;
    const __nv_bfloat16* Qhg = g_Qh + hoff;
    const __nv_bfloat16* Qlg = g_Ql + hoff;
    const __nv_bfloat16* Khg = g_Kh + hoff;
    const __nv_bfloat16* Klg = g_Kl + hoff;
    const __nv_bfloat16* Vhg = g_Vh + hoff;
    const __nv_bfloat16* Vlg = g_Vl + hoff;

    // load Q tile (128 x 128 halves, hi+lo): 16 chunks/thread
#pragma unroll
    for (int arr = 0; arr < 2; arr++) {
        const __nv_bfloat16* src = arr ? Qlg : Qhg;
        uint32_t dbase = sbase + (arr ? AQL : AQH) * 4;
#pragma unroll
        for (int i = 0; i < 8; i++) {
            int idx = tid + i * 256;
            int row = idx >> 4;
            int c   = idx & 15;
            CP_ASYNC16(dbase + row * 272 + c * 16,
                       (const void*)(src + (size_t)(q0 + row) * HD + c * 8));
        }
    }
    CP_COMMIT();

    float m0 = -1e30f, m1 = -1e30f, l0 = 0.f, l1 = 0.f;
    float o[16][4];
#pragma unroll
    for (int i = 0; i < 16; i++)
#pragma unroll
        for (int j = 0; j < 4; j++) o[i][j] = 0.f;

    const float scl = 0.08838834764831845f;   // 1/sqrt(128)
    const int NTk = 2 * qt + 2;

    for (int jt = 0; jt < NTk; jt++) {
        const int k0 = jt * 64;
        __syncthreads();   // previous tile's consumers done

        // K tile (64 x 128 halves, hi+lo): cp.async, 8 chunks/thread
#pragma unroll
        for (int arr = 0; arr < 2; arr++) {
            const __nv_bfloat16* src = arr ? Klg : Khg;
            uint32_t dbase = sbase + (arr ? AKL : AKH) * 4;
#pragma unroll
            for (int i = 0; i < 4; i++) {
                int idx = tid + i * 256;
                int row = idx >> 4;
                int c   = idx & 15;
                CP_ASYNC16(dbase + row * 272 + c * 16,
                           (const void*)(src + (size_t)(k0 + row) * HD + c * 8));
            }
        }
        CP_COMMIT();

        // V tile -> smem transposed as packed key-pairs: Vt[d][kp] u32
        {
            const int kp  = tid & 31;          // key pair 0..31
            const int dcb = tid >> 5;          // base d-chunk 0..7
#pragma unroll
            for (int arr = 0; arr < 2; arr++) {
                const __nv_bfloat16* src = arr ? Vlg : Vhg;
                const int vb = arr ? AVL : AVH;
#pragma unroll
                for (int ds = 0; ds < 2; ds++) {
                    int dc = dcb + ds * 8;     // d-chunk 0..15
                    uint4 a = *(const uint4*)(src + (size_t)(k0 + 2 * kp) * HD + dc * 8);
                    uint4 b = *(const uint4*)(src + (size_t)(k0 + 2 * kp + 1) * HD + dc * 8);
                    int base = vb + (dc * 8) * 36 + kp;
                    S32[base + 0 * 36] = __byte_perm(a.x, b.x, 0x5410);
                    S32[base + 1 * 36] = __byte_perm(a.x, b.x, 0x7632);
                    S32[base + 2 * 36] = __byte_perm(a.y, b.y, 0x5410);
                    S32[base + 3 * 36] = __byte_perm(a.y, b.y, 0x7632);
                    S32[base + 4 * 36] = __byte_perm(a.z, b.z, 0x5410);
                    S32[base + 5 * 36] = __byte_perm(a.z, b.z, 0x7632);
                    S32[base + 6 * 36] = __byte_perm(a.w, b.w, 0x5410);
                    S32[base + 7 * 36] = __byte_perm(a.w, b.w, 0x7632);
                }
            }
        }
        CP_WAIT(0);
        __syncthreads();

        // skip warps whose entire row range is below this key tile (fully masked)
        if (k0 <= q0 + wid * 16 + 15) {
            // ---- S = Q K^T (3 passes) ----
            float sacc[8][4];
#pragma unroll
            for (int nb = 0; nb < 8; nb++)
#pragma unroll
                for (int e = 0; e < 4; e++) sacc[nb][e] = 0.f;

            const int r0 = wid * 16 + fr;
#pragma unroll
            for (int pass = 0; pass < 3; pass++) {
                const int qb = (pass == 2) ? AQL : AQH;
                const int kb = (pass == 1) ? AKL : AKH;
#pragma unroll
                for (int kc = 0; kc < 8; kc++) {
                    const int colu = kc * 8 + fq;
                    uint32_t a[4];
                    a[0] = S32[qb + r0 * 68 + colu];
                    a[1] = S32[qb + (r0 + 8) * 68 + colu];
                    a[2] = S32[qb + r0 * 68 + colu + 4];
                    a[3] = S32[qb + (r0 + 8) * 68 + colu + 4];
#pragma unroll
                    for (int nb = 0; nb < 8; nb++) {
                        uint32_t b[2];
                        int rn = nb * 8 + fr;
                        b[0] = S32[kb + rn * 68 + colu];
                        b[1] = S32[kb + rn * 68 + colu + 4];
                        mma_bf16(sacc[nb], a, b);
                    }
                }
            }

            // ---- scale + causal mask ----
            const bool need_mask = (jt >= 2 * qt);
            const int gq0 = q0 + r0;
#pragma unroll
            for (int nb = 0; nb < 8; nb++) {
#pragma unroll
                for (int e = 0; e < 4; e++) {
                    float s = sacc[nb][e] * scl;
                    if (need_mask) {
                        int gq = gq0 + ((e >= 2) ? 8 : 0);
                        int gk = k0 + nb * 8 + 2 * fq + (e & 1);
                        if (gk > gq) s = -1e30f;
                    }
                    sacc[nb][e] = s;
                }
            }

            // ---- online softmax (registers + quad shuffles) ----
            float t0 = -1e30f, t1 = -1e30f;
#pragma unroll
            for (int nb = 0; nb < 8; nb++) {
                t0 = fmaxf(t0, fmaxf(sacc[nb][0], sacc[nb][1]));
                t1 = fmaxf(t1, fmaxf(sacc[nb][2], sacc[nb][3]));
            }
            t0 = fmaxf(t0, __shfl_xor_sync(0xffffffffu, t0, 1));
            t0 = fmaxf(t0, __shfl_xor_sync(0xffffffffu, t0, 2));
            t1 = fmaxf(t1, __shfl_xor_sync(0xffffffffu, t1, 1));
            t1 = fmaxf(t1, __shfl_xor_sync(0xffffffffu, t1, 2));
            float mn0 = fmaxf(m0, t0), mn1 = fmaxf(m1, t1);
            float al0 = __expf(m0 - mn0), al1 = __expf(m1 - mn1);
            float s0 = 0.f, s1 = 0.f;
#pragma unroll
            for (int nb = 0; nb < 8; nb++) {
                float p;
                p = __expf(sacc[nb][0] - mn0); sacc[nb][0] = p; s0 += p;
                p = __expf(sacc[nb][1] - mn0); sacc[nb][1] = p; s0 += p;
                p = __expf(sacc[nb][2] - mn1); sacc[nb][2] = p; s1 += p;
                p = __expf(sacc[nb][3] - mn1); sacc[nb][3] = p; s1 += p;
            }
            s0 += __shfl_xor_sync(0xffffffffu, s0, 1);
            s0 += __shfl_xor_sync(0xffffffffu, s0, 2);
            s1 += __shfl_xor_sync(0xffffffffu, s1, 1);
            s1 += __shfl_xor_sync(0xffffffffu, s1, 2);
            l0 = l0 * al0 + s0;  l1 = l1 * al1 + s1;
            m0 = mn0;  m1 = mn1;

            // rescale O
#pragma unroll
            for (int db = 0; db < 16; db++) {
                o[db][0] *= al0; o[db][1] *= al0;
                o[db][2] *= al1; o[db][3] *= al1;
            }

            // ---- pack P as A-fragments (hi/lo), in registers ----
            uint32_t pah[4][4], pal[4][4];
#pragma unroll
            for (int kc2 = 0; kc2 < 4; kc2++) {
                int n0 = 2 * kc2, n1 = n0 + 1;
                pack_hl(sacc[n0][0], sacc[n0][1], pah[kc2][0], pal[kc2][0]);
                pack_hl(sacc[n0][2], sacc[n0][3], pah[kc2][1], pal[kc2][1]);
                pack_hl(sacc[n1][0], sacc[n1][1], pah[kc2][2], pal[kc2][2]);
                pack_hl(sacc[n1][2], sacc[n1][3], pah[kc2][3], pal[kc2][3]);
            }

            // ---- O += P V (3 passes) ----
#pragma unroll
            for (int pass = 0; pass < 3; pass++) {
                const int vb = (pass == 1) ? AVL : AVH;
#pragma unroll
                for (int kc2 = 0; kc2 < 4; kc2++) {
                    const uint32_t* pa = (pass == 2) ? pal[kc2] : pah[kc2];
                    const int colu = kc2 * 8 + fq;
#pragma unroll
                    for (int db = 0; db < 16; db++) {
                        uint32_t b[2];
                        int rn = db * 8 + fr;
                        b[0] = S32[vb + rn * 36 + colu];
                        b[1] = S32[vb + rn * 36 + colu + 4];
                        mma_bf16(o[db], pa, b);
                    }
                }
            }
        }
    }

    // ---- epilogue: O/l -> g_Oh/g_Ol (hi/lo bf16, row-major [M][2048]) ----
    const int b    = bh >> 4;
    const int head = bh & 15;
    const int row0 = b * NS + q0 + wid * 16 + fr;
    const int col0 = head * HD + 2 * fq;
    const float li0 = 1.f / l0, li1 = 1.f / l1;
#pragma unroll
    for (int db = 0; db < 16; db++) {
        uint32_t h, l;
        size_t i0 = (size_t)row0 * NHID + col0 + db * 8;
        pack_hl(o[db][0] * li0, o[db][1] * li0, h, l);
        *(uint32_t*)&g_Oh[i0] = h;
        *(uint32_t*)&g_Ol[i0] = l;
        size_t i1 = i0 + (size_t)8 * NHID;
        pack_hl(o[db][2] * li1, o[db][3] * li1, h, l);
        *(uint32_t*)&g_Oh[i1] = h;
        *(uint32_t*)&g_Ol[i1] = l;
    }
}

// ---------------------------------------------------------------------------
extern "C" void kernel_launch(void* const* d_in, const int* in_sizes, int n_in,
                              void* d_out, int out_size)
{
    const float* x    = (const float*)d_in[0];
    const float* Wqkv = (const float*)d_in[1];
    const float* bqkv = (const float*)d_in[2];
    const float* Wo   = (const float*)d_in[3];
    const float* bo   = (const float*)d_in[4];
    float* out = (float*)d_out;

    cudaFuncSetAttribute(attn_mma, cudaFuncAttributeMaxDynamicSharedMemorySize,
                         (int)ATTN_SMEM);
    cudaFuncSetAttribute(gemm_mma<0>, cudaFuncAttributeMaxDynamicSharedMemorySize,
                         (int)GEMM_SMEM);
    cudaFuncSetAttribute(gemm_mma<1>, cudaFuncAttributeMaxDynamicSharedMemorySize,
                         (int)GEMM_SMEM);

    // hi/lo splits (+ weight transposes to [N][K] K-major)
    split_x_kernel<<<(M_TOT * NHID) / 1024, 256>>>(x);
    split_tr_kernel<0><<<dim3(N3 / 32, NHID / 32), dim3(32, 8)>>>(Wqkv);
    split_tr_kernel<1><<<dim3(NHID / 32, NHID / 32), dim3(32, 8)>>>(Wo);

    // 1) QKV projection (HMMA), writes Q/K/V hi/lo bf16 per head
    gemm_mma<0><<<dim3(N3 / 128, M_TOT / 128), 256, GEMM_SMEM>>>(bqkv, nullptr);

    // 2) causal attention (HMMA), writes O hi/lo bf16
    attn_mma<<<dim3(NS / 128, NB * NHEADS), 256, ATTN_SMEM>>>();

    // 3) output projection (HMMA)
    gemm_mma<1><<<dim3(NHID / 128, M_TOT / 128), 256, GEMM_SMEM>>>(bo, out);
}